// round 1
// baseline (speedup 1.0000x reference)
#include <cuda_runtime.h>
#include <math.h>

#define H 128
#define W 128
#define TILE 32
#define MAXN 16384
#define NTILES 16
#define TERM_T 1.0e-8f

// ---------------- scratch (device globals; no allocation) ----------------
__device__ float  g_depth[MAXN];

// unsorted per-gaussian params
__device__ float4 g_u1[MAXN];   // mx, my, conA, conB(=sc01+sc10)
__device__ float4 g_u2[MAXN];   // conC, opacity, depth, colR
__device__ float2 g_u3[MAXN];   // colG, colB
__device__ float4 g_u4[MAXN];   // rminx, rminy, rmaxx, rmaxy

// depth-sorted
__device__ float4 g_s1[MAXN];
__device__ float4 g_s2[MAXN];
__device__ float2 g_s3[MAXN];
__device__ float4 g_s4[MAXN];

// per-tile compacted, depth-ordered lists
__device__ float4 g_q1[NTILES][MAXN];
__device__ float4 g_q2[NTILES][MAXN];
__device__ float2 g_q3[NTILES][MAXN];
__device__ int    g_tileCount[NTILES];

// ---------------- kernel 1: preprocess ----------------
__global__ void prep_kernel(const float* __restrict__ means,
                            const float* __restrict__ cov,
                            const float* __restrict__ color,
                            const float* __restrict__ opacity,
                            const float* __restrict__ depths,
                            int n)
{
    int i = blockIdx.x * blockDim.x + threadIdx.x;
    if (i >= n) return;

    float mx  = means[2*i+0];
    float my  = means[2*i+1];
    float c00 = cov[4*i+0];
    float c01 = cov[4*i+1];
    float c10 = cov[4*i+2];
    float c11 = cov[4*i+3];

    // match JAX's mul/sub sequencing exactly (no fma contraction) —
    // this feeds the strict-inequality tile mask via radii.
    float det = __fsub_rn(__fmul_rn(c00, c11), __fmul_rn(c01, c10));
    float mid = __fmul_rn(0.5f, __fadd_rn(c00, c11));
    float s   = sqrtf(fmaxf(__fsub_rn(__fmul_rn(mid, mid), det), 0.1f));
    float lam = fmaxf(__fadd_rn(mid, s), __fsub_rn(mid, s));
    float radii = __fmul_rn(3.0f, ceilf(sqrtf(lam)));

    float rminx = fminf(fmaxf(__fsub_rn(mx, radii), 0.0f), (float)(W-1));
    float rminy = fminf(fmaxf(__fsub_rn(my, radii), 0.0f), (float)(H-1));
    float rmaxx = fminf(fmaxf(__fadd_rn(mx, radii), 0.0f), (float)(W-1));
    float rmaxy = fminf(fmaxf(__fadd_rn(my, radii), 0.0f), (float)(H-1));

    float inv = __fdiv_rn(1.0f, det);
    float ca  = __fmul_rn(c11, inv);               // sc00
    float cc  = __fmul_rn(c00, inv);               // sc11
    // sc01 + sc10 = (-c01)*inv + (-c10)*inv
    float cb  = __fadd_rn(__fmul_rn(-c01, inv), __fmul_rn(-c10, inv));

    float dep = depths[i];

    g_depth[i] = dep;
    g_u1[i] = make_float4(mx, my, ca, cb);
    g_u2[i] = make_float4(cc, opacity[i], dep, color[3*i+0]);
    g_u3[i] = make_float2(color[3*i+1], color[3*i+2]);
    g_u4[i] = make_float4(rminx, rminy, rmaxx, rmaxy);
}

// ---------------- kernel 2: O(N^2) stable rank + scatter ----------------
__global__ void rank_scatter_kernel(int n)
{
    __shared__ float sd[256];
    int i  = blockIdx.x * blockDim.x + threadIdx.x;
    float di = (i < n) ? g_depth[i] : 0.0f;
    int rank = 0;

    for (int base = 0; base < n; base += 256) {
        int j = base + threadIdx.x;
        sd[threadIdx.x] = (j < n) ? g_depth[j] : 3.0e38f;
        __syncthreads();
        int lim = min(256, n - base);
        #pragma unroll 8
        for (int k = 0; k < lim; ++k) {
            float dj = sd[k];
            int   jj = base + k;
            rank += (dj < di) || (dj == di && jj < i);
        }
        __syncthreads();
    }

    if (i < n) {
        g_s1[rank] = g_u1[i];
        g_s2[rank] = g_u2[i];
        g_s3[rank] = g_u3[i];
        g_s4[rank] = g_u4[i];
    }
}

// ---------------- kernel 3: per-tile stable compaction ----------------
__global__ void tile_build_kernel(int n)
{
    int tile = blockIdx.x;
    float wlo = (float)((tile & 3) * TILE);
    float whi = wlo + (float)(TILE - 1);
    float hlo = (float)((tile >> 2) * TILE);
    float hhi = hlo + (float)(TILE - 1);

    __shared__ int warpCnt[8];
    int tid  = threadIdx.x;
    int lane = tid & 31;
    int warp = tid >> 5;
    int total = 0;

    for (int base = 0; base < n; base += 256) {
        int i = base + tid;
        bool m = false;
        if (i < n) {
            float4 r = g_s4[i];
            float tlx = fmaxf(r.x, wlo);
            float tly = fmaxf(r.y, hlo);
            float brx = fminf(r.z, whi);
            float bry = fminf(r.w, hhi);
            m = (brx > tlx) && (bry > tly);
        }
        unsigned ball = __ballot_sync(0xffffffffu, m);
        int pre = __popc(ball & ((1u << lane) - 1u));
        if (lane == 0) warpCnt[warp] = __popc(ball);
        __syncthreads();
        int woff = 0, batchTotal = 0;
        #pragma unroll
        for (int w = 0; w < 8; ++w) {
            int c = warpCnt[w];
            if (w < warp) woff += c;
            batchTotal += c;
        }
        if (m) {
            int pos = total + woff + pre;
            g_q1[tile][pos] = g_s1[i];
            g_q2[tile][pos] = g_s2[i];
            g_q3[tile][pos] = g_s3[i];
        }
        total += batchTotal;
        __syncthreads();
    }
    if (tid == 0) g_tileCount[tile] = total;
}

// ---------------- kernel 4: render ----------------
#define BATCH 256
__global__ void __launch_bounds__(256, 2) render_kernel(float* __restrict__ out)
{
    int tilex = blockIdx.x;
    int tiley = blockIdx.y;
    int tile  = tiley * 4 + tilex;
    int px = tilex * TILE + threadIdx.x;
    int py = tiley * TILE + blockIdx.z * 8 + threadIdx.y;
    float fx = (float)px;
    float fy = (float)py;

    int cnt = g_tileCount[tile];

    __shared__ float4 sb1[BATCH];
    __shared__ float4 sb2[BATCH];
    __shared__ float2 sb3[BATCH];

    float T = 1.0f;
    float cr = 0.0f, cg = 0.0f, cbl = 0.0f, cd = 0.0f, cacc = 0.0f;
    int tid = threadIdx.y * 32 + threadIdx.x;

    for (int base = 0; base < cnt; base += BATCH) {
        int m = min(BATCH, cnt - base);
        if (tid < m) {
            sb1[tid] = g_q1[tile][base + tid];
            sb2[tid] = g_q2[tile][base + tid];
            sb3[tid] = g_q3[tile][base + tid];
        }
        __syncthreads();

        if (T >= TERM_T) {
            for (int k = 0; k < m; ++k) {
                float4 p1 = sb1[k];
                float4 p2 = sb2[k];
                float dx = fx - p1.x;
                float dy = fy - p1.y;
                float power = dx * dx * p1.z + dy * dy * p2.x + dx * dy * p1.w;
                float gw = expf(-0.5f * power);
                float alpha = fminf(gw * p2.y, 0.99f);
                float wgt = T * alpha;
                float2 p3 = sb3[k];
                cr   += wgt * p2.w;
                cg   += wgt * p3.x;
                cbl  += wgt * p3.y;
                cd   += wgt * p2.z;
                cacc += wgt;
                T *= (1.0f - alpha);
                if (T < TERM_T) break;
            }
        }
        __syncthreads();
        if (__syncthreads_and(T < TERM_T)) break;
    }

    int pix = py * W + px;
    float bg = 1.0f - cacc;
    out[pix * 3 + 0]     = cr  + bg;
    out[pix * 3 + 1]     = cg  + bg;
    out[pix * 3 + 2]     = cbl + bg;
    out[H * W * 3 + pix] = cd;
    out[H * W * 4 + pix] = cacc;
}

// ---------------- launch ----------------
extern "C" void kernel_launch(void* const* d_in, const int* in_sizes, int n_in,
                              void* d_out, int out_size)
{
    const float* means   = (const float*)d_in[0];
    const float* cov     = (const float*)d_in[1];
    const float* color   = (const float*)d_in[2];
    const float* opacity = (const float*)d_in[3];
    const float* depths  = (const float*)d_in[4];
    int n = in_sizes[4];
    if (n > MAXN) n = MAXN;

    int blocks = (n + 255) / 256;
    prep_kernel<<<blocks, 256>>>(means, cov, color, opacity, depths, n);
    rank_scatter_kernel<<<blocks, 256>>>(n);
    tile_build_kernel<<<NTILES, 256>>>(n);
    render_kernel<<<dim3(4, 4, 4), dim3(32, 8)>>>((float*)d_out);
}

// round 2
// speedup vs baseline: 1.7239x; 1.7239x over previous
#include <cuda_runtime.h>
#include <math.h>

#define H 128
#define W 128
#define TILE 32
#define MAXN 16384
#define NTILES 16
#define TERM_T 1.0e-8f
#define JSLICES 8

// ---------------- scratch (device globals; no allocation) ----------------
__device__ unsigned long long g_key[MAXN];   // (depth_bits<<32)|index : stable sort key
__device__ int    g_rank[MAXN];

// unsorted per-gaussian params
__device__ float4 g_u1[MAXN];   // mx, my, conA, conB(=sc01+sc10)
__device__ float4 g_u2[MAXN];   // conC, opacity, depth, colR
__device__ float2 g_u3[MAXN];   // colG, colB
__device__ float4 g_u4[MAXN];   // rminx, rminy, rmaxx, rmaxy

// depth-sorted
__device__ float4 g_s1[MAXN];
__device__ float4 g_s2[MAXN];
__device__ float2 g_s3[MAXN];
__device__ float4 g_s4[MAXN];

// per-tile compacted, depth-ordered lists
__device__ float4 g_q1[NTILES][MAXN];
__device__ float4 g_q2[NTILES][MAXN];
__device__ float2 g_q3[NTILES][MAXN];
__device__ int    g_tileCount[NTILES];

// ---------------- kernel 1: preprocess ----------------
__global__ void prep_kernel(const float* __restrict__ means,
                            const float* __restrict__ cov,
                            const float* __restrict__ color,
                            const float* __restrict__ opacity,
                            const float* __restrict__ depths,
                            int n)
{
    int i = blockIdx.x * blockDim.x + threadIdx.x;
    if (i >= n) return;

    float mx  = means[2*i+0];
    float my  = means[2*i+1];
    float c00 = cov[4*i+0];
    float c01 = cov[4*i+1];
    float c10 = cov[4*i+2];
    float c11 = cov[4*i+3];

    // match JAX's mul/sub sequencing exactly (no fma contraction) —
    // this feeds the strict-inequality tile mask via radii.
    float det = __fsub_rn(__fmul_rn(c00, c11), __fmul_rn(c01, c10));
    float mid = __fmul_rn(0.5f, __fadd_rn(c00, c11));
    float s   = sqrtf(fmaxf(__fsub_rn(__fmul_rn(mid, mid), det), 0.1f));
    float lam = fmaxf(__fadd_rn(mid, s), __fsub_rn(mid, s));
    float radii = __fmul_rn(3.0f, ceilf(sqrtf(lam)));

    float rminx = fminf(fmaxf(__fsub_rn(mx, radii), 0.0f), (float)(W-1));
    float rminy = fminf(fmaxf(__fsub_rn(my, radii), 0.0f), (float)(H-1));
    float rmaxx = fminf(fmaxf(__fadd_rn(mx, radii), 0.0f), (float)(W-1));
    float rmaxy = fminf(fmaxf(__fadd_rn(my, radii), 0.0f), (float)(H-1));

    float inv = __fdiv_rn(1.0f, det);
    float ca  = __fmul_rn(c11, inv);               // sc00
    float cc  = __fmul_rn(c00, inv);               // sc11
    float cb  = __fadd_rn(__fmul_rn(-c01, inv), __fmul_rn(-c10, inv));

    float dep = depths[i];
    // depths are strictly positive -> float bits are order-preserving as uint
    unsigned int db = __float_as_uint(dep);
    g_key[i]  = ((unsigned long long)db << 32) | (unsigned int)i;
    g_rank[i] = 0;

    g_u1[i] = make_float4(mx, my, ca, cb);
    g_u2[i] = make_float4(cc, opacity[i], dep, color[3*i+0]);
    g_u3[i] = make_float2(color[3*i+1], color[3*i+2]);
    g_u4[i] = make_float4(rminx, rminy, rmaxx, rmaxy);
}

// ---------------- kernel 2a: partial stable rank (j sliced across blockIdx.y) ----
__global__ void rank_partial_kernel(int n, int slice)
{
    __shared__ unsigned long long sk[256];
    int i  = blockIdx.x * blockDim.x + threadIdx.x;
    unsigned long long ki = (i < n) ? g_key[i] : 0ull;
    int rank = 0;

    int jb = blockIdx.y * slice;
    int je = min(n, jb + slice);

    for (int base = jb; base < je; base += 256) {
        int j = base + threadIdx.x;
        sk[threadIdx.x] = (j < je) ? g_key[j] : ~0ull;
        __syncthreads();
        int lim = min(256, je - base);
        #pragma unroll 8
        for (int k = 0; k < lim; ++k) {
            rank += (sk[k] < ki);
        }
        __syncthreads();
    }

    if (i < n && rank) atomicAdd(&g_rank[i], rank);
}

// ---------------- kernel 2b: scatter into depth order ----------------
__global__ void scatter_kernel(int n)
{
    int i = blockIdx.x * blockDim.x + threadIdx.x;
    if (i >= n) return;
    int r = g_rank[i];
    g_s1[r] = g_u1[i];
    g_s2[r] = g_u2[i];
    g_s3[r] = g_u3[i];
    g_s4[r] = g_u4[i];
}

// ---------------- kernel 3: per-tile stable compaction ----------------
#define TB_THREADS 1024
__global__ void __launch_bounds__(TB_THREADS) tile_build_kernel(int n)
{
    int tile = blockIdx.x;
    float wlo = (float)((tile & 3) * TILE);
    float whi = wlo + (float)(TILE - 1);
    float hlo = (float)((tile >> 2) * TILE);
    float hhi = hlo + (float)(TILE - 1);

    __shared__ int warpCnt[TB_THREADS / 32];
    int tid  = threadIdx.x;
    int lane = tid & 31;
    int warp = tid >> 5;
    int total = 0;

    for (int base = 0; base < n; base += TB_THREADS) {
        int i = base + tid;
        bool m = false;
        if (i < n) {
            float4 r = g_s4[i];
            float tlx = fmaxf(r.x, wlo);
            float tly = fmaxf(r.y, hlo);
            float brx = fminf(r.z, whi);
            float bry = fminf(r.w, hhi);
            m = (brx > tlx) && (bry > tly);
        }
        unsigned ball = __ballot_sync(0xffffffffu, m);
        int pre = __popc(ball & ((1u << lane) - 1u));
        if (lane == 0) warpCnt[warp] = __popc(ball);
        __syncthreads();
        int woff = 0, batchTotal = 0;
        #pragma unroll
        for (int w = 0; w < TB_THREADS / 32; ++w) {
            int c = warpCnt[w];
            woff += (w < warp) ? c : 0;
            batchTotal += c;
        }
        if (m) {
            int pos = total + woff + pre;
            g_q1[tile][pos] = g_s1[i];
            g_q2[tile][pos] = g_s2[i];
            g_q3[tile][pos] = g_s3[i];
        }
        total += batchTotal;
        __syncthreads();
    }
    if (tid == 0) g_tileCount[tile] = total;
}

// ---------------- kernel 4: render ----------------
#define BATCH 128
__global__ void __launch_bounds__(128) render_kernel(float* __restrict__ out)
{
    int tilex = blockIdx.x;
    int tiley = blockIdx.y;
    int tile  = tiley * 4 + tilex;
    int px = tilex * TILE + threadIdx.x;
    int py = tiley * TILE + blockIdx.z * 4 + threadIdx.y;
    float fx = (float)px;
    float fy = (float)py;

    int cnt = g_tileCount[tile];

    __shared__ float4 sb1[BATCH];
    __shared__ float4 sb2[BATCH];
    __shared__ float2 sb3[BATCH];

    float T = 1.0f;
    float cr = 0.0f, cg = 0.0f, cbl = 0.0f, cd = 0.0f, cacc = 0.0f;
    int tid = threadIdx.y * 32 + threadIdx.x;

    for (int base = 0; base < cnt; base += BATCH) {
        int m = min(BATCH, cnt - base);
        if (tid < m) {
            sb1[tid] = g_q1[tile][base + tid];
            sb2[tid] = g_q2[tile][base + tid];
            sb3[tid] = g_q3[tile][base + tid];
        }
        __syncthreads();

        if (T >= TERM_T) {
            for (int k = 0; k < m; ++k) {
                float4 p1 = sb1[k];
                float4 p2 = sb2[k];
                float dx = fx - p1.x;
                float dy = fy - p1.y;
                float power = dx * dx * p1.z + dy * dy * p2.x + dx * dy * p1.w;
                float gw = __expf(-0.5f * power);
                float alpha = fminf(gw * p2.y, 0.99f);
                float wgt = T * alpha;
                float2 p3 = sb3[k];
                cr   += wgt * p2.w;
                cg   += wgt * p3.x;
                cbl  += wgt * p3.y;
                cd   += wgt * p2.z;
                cacc += wgt;
                T *= (1.0f - alpha);
                if (T < TERM_T) break;
            }
        }
        __syncthreads();
        if (__syncthreads_and(T < TERM_T)) break;
    }

    int pix = py * W + px;
    float bg = 1.0f - cacc;
    out[pix * 3 + 0]     = cr  + bg;
    out[pix * 3 + 1]     = cg  + bg;
    out[pix * 3 + 2]     = cbl + bg;
    out[H * W * 3 + pix] = cd;
    out[H * W * 4 + pix] = cacc;
}

// ---------------- launch ----------------
extern "C" void kernel_launch(void* const* d_in, const int* in_sizes, int n_in,
                              void* d_out, int out_size)
{
    const float* means   = (const float*)d_in[0];
    const float* cov     = (const float*)d_in[1];
    const float* color   = (const float*)d_in[2];
    const float* opacity = (const float*)d_in[3];
    const float* depths  = (const float*)d_in[4];
    int n = in_sizes[4];
    if (n > MAXN) n = MAXN;

    int blocks = (n + 255) / 256;
    int slice = ((n + JSLICES - 1) / JSLICES + 255) & ~255;

    prep_kernel<<<blocks, 256>>>(means, cov, color, opacity, depths, n);
    rank_partial_kernel<<<dim3(blocks, JSLICES), 256>>>(n, slice);
    scatter_kernel<<<blocks, 256>>>(n);
    tile_build_kernel<<<NTILES, TB_THREADS>>>(n);
    render_kernel<<<dim3(4, 4, 8), dim3(32, 4)>>>((float*)d_out);
}

// round 3
// speedup vs baseline: 2.4090x; 1.3974x over previous
#include <cuda_runtime.h>
#include <math.h>

#define H 128
#define W 128
#define TILE 32
#define MAXN 16384
#define NTILES 16
#define NB 4096
#define NCHUNK_MAX 64
#define TERM_T 1.0e-8f
#define SKIP_L2 -23.25f   // log2(1e-7) ~ -23.25; power below this -> alpha < 1e-7

__device__ __forceinline__ float ex2f(float x) {
    float y; asm("ex2.approx.ftz.f32 %0, %1;" : "=f"(y) : "f"(x)); return y;
}

// ---------------- scratch (device globals; no allocation) ----------------
__device__ unsigned long long g_key [MAXN];   // (depth_bits<<32)|index
__device__ int                g_bucket[MAXN];
__device__ int                g_bucketCnt[NB];
__device__ int                g_bucketOff[NB];
__device__ int                g_cursor[NB];
__device__ unsigned long long g_bkey[MAXN];   // keys grouped by bucket

// unsorted per-gaussian params (indexed by original i)
__device__ float4 g_u1[MAXN];   // mx, my, A', B'   (conic pre-scaled by -0.5*log2e)
__device__ float4 g_u2[MAXN];   // C', log2(opacity), depth, colR
__device__ float2 g_u3[MAXN];   // colG, colB
__device__ float4 g_u4[MAXN];   // rminx, rminy, rmaxx, rmaxy

// depth-sorted
__device__ float4 g_s1[MAXN];
__device__ float4 g_s2[MAXN];
__device__ float2 g_s3[MAXN];
__device__ float4 g_s4[MAXN];

// tile build
__device__ int g_chunkCnt[NTILES][NCHUNK_MAX];
__device__ int g_chunkOff[NTILES][NCHUNK_MAX];
__device__ int g_tileCount[NTILES];

// per-tile compacted, depth-ordered lists
__device__ float4 g_q1[NTILES][MAXN];
__device__ float4 g_q2[NTILES][MAXN];
__device__ float2 g_q3[NTILES][MAXN];

// ---------------- kernel 0: zero bucket counters ----------------
__global__ void zero_kernel()
{
    int i = blockIdx.x * blockDim.x + threadIdx.x;
    if (i < NB) g_bucketCnt[i] = 0;
}

// ---------------- kernel 1: preprocess + bucket count ----------------
__global__ void prep_kernel(const float* __restrict__ means,
                            const float* __restrict__ cov,
                            const float* __restrict__ color,
                            const float* __restrict__ opacity,
                            const float* __restrict__ depths,
                            int n)
{
    int i = blockIdx.x * blockDim.x + threadIdx.x;
    if (i >= n) return;

    float mx  = means[2*i+0];
    float my  = means[2*i+1];
    float c00 = cov[4*i+0];
    float c01 = cov[4*i+1];
    float c10 = cov[4*i+2];
    float c11 = cov[4*i+3];

    // match JAX sequencing for the mask-critical radii math
    float det = __fsub_rn(__fmul_rn(c00, c11), __fmul_rn(c01, c10));
    float mid = __fmul_rn(0.5f, __fadd_rn(c00, c11));
    float s   = sqrtf(fmaxf(__fsub_rn(__fmul_rn(mid, mid), det), 0.1f));
    float lam = fmaxf(__fadd_rn(mid, s), __fsub_rn(mid, s));
    float radii = __fmul_rn(3.0f, ceilf(sqrtf(lam)));

    float rminx = fminf(fmaxf(__fsub_rn(mx, radii), 0.0f), (float)(W-1));
    float rminy = fminf(fmaxf(__fsub_rn(my, radii), 0.0f), (float)(H-1));
    float rmaxx = fminf(fmaxf(__fadd_rn(mx, radii), 0.0f), (float)(W-1));
    float rmaxy = fminf(fmaxf(__fadd_rn(my, radii), 0.0f), (float)(H-1));

    float inv = __fdiv_rn(1.0f, det);
    const float L = -0.72134752044448170368f;  // -0.5 * log2(e)
    float ca = __fmul_rn(c11, inv) * L;                                    // A'
    float cc = __fmul_rn(c00, inv) * L;                                    // C'
    float cb = __fadd_rn(__fmul_rn(-c01, inv), __fmul_rn(-c10, inv)) * L;  // B'

    float dep = depths[i];
    float op  = opacity[i];
    float ol2 = log2f(op);

    unsigned int db = __float_as_uint(dep);   // depths > 0 -> order-preserving bits
    g_key[i] = ((unsigned long long)db << 32) | (unsigned int)i;

    int b = (int)((dep - 0.19f) * 400.0f);
    b = max(0, min(NB - 1, b));
    g_bucket[i] = b;
    atomicAdd(&g_bucketCnt[b], 1);

    g_u1[i] = make_float4(mx, my, ca, cb);
    g_u2[i] = make_float4(cc, ol2, dep, color[3*i+0]);
    g_u3[i] = make_float2(color[3*i+1], color[3*i+2]);
    g_u4[i] = make_float4(rminx, rminy, rmaxx, rmaxy);
}

// ---------------- kernel 2: exclusive scan of 4096 bucket counts ----------------
__global__ void __launch_bounds__(1024) bucket_scan_kernel()
{
    __shared__ int sums[1024];
    int t = threadIdx.x;
    int c0 = g_bucketCnt[4*t+0];
    int c1 = g_bucketCnt[4*t+1];
    int c2 = g_bucketCnt[4*t+2];
    int c3 = g_bucketCnt[4*t+3];
    int s = c0 + c1 + c2 + c3;
    sums[t] = s;
    __syncthreads();
    for (int d = 1; d < 1024; d <<= 1) {
        int v = (t >= d) ? sums[t - d] : 0;
        __syncthreads();
        sums[t] += v;
        __syncthreads();
    }
    int e = sums[t] - s;     // exclusive prefix of this thread's group
    g_bucketOff[4*t+0] = e;            g_cursor[4*t+0] = e;
    g_bucketOff[4*t+1] = e + c0;       g_cursor[4*t+1] = e + c0;
    g_bucketOff[4*t+2] = e + c0 + c1;  g_cursor[4*t+2] = e + c0 + c1;
    g_bucketOff[4*t+3] = e + c0+c1+c2; g_cursor[4*t+3] = e + c0 + c1 + c2;
}

// ---------------- kernel 3: place keys into bucket regions ----------------
__global__ void place_kernel(int n)
{
    int i = blockIdx.x * blockDim.x + threadIdx.x;
    if (i >= n) return;
    int b = g_bucket[i];
    int slot = atomicAdd(&g_cursor[b], 1);
    g_bkey[slot] = g_key[i];
}

// ---------------- kernel 4: within-bucket stable rank + scatter ----------------
__global__ void rank_scatter_kernel(int n)
{
    int i = blockIdx.x * blockDim.x + threadIdx.x;
    if (i >= n) return;
    int b = g_bucket[i];
    unsigned long long ki = g_key[i];
    int off = g_bucketOff[b];
    int cnt = g_bucketCnt[b];
    int r = off;
    for (int j = off; j < off + cnt; ++j)
        r += (g_bkey[j] < ki);
    g_s1[r] = g_u1[i];
    g_s2[r] = g_u2[i];
    g_s3[r] = g_u3[i];
    g_s4[r] = g_u4[i];
}

// ---------------- tile mask helper ----------------
__device__ __forceinline__ bool tile_mask(float4 r, int tile)
{
    float wlo = (float)((tile & 3) * TILE);
    float hlo = (float)((tile >> 2) * TILE);
    float tlx = fmaxf(r.x, wlo);
    float tly = fmaxf(r.y, hlo);
    float brx = fminf(r.z, wlo + (float)(TILE - 1));
    float bry = fminf(r.w, hlo + (float)(TILE - 1));
    return (brx > tlx) && (bry > tly);
}

// ---------------- kernel 5: per-(chunk,tile) mask counts ----------------
__global__ void tb_count_kernel(int n)
{
    int chunk = blockIdx.x;
    int tile  = blockIdx.y;
    int i = chunk * 256 + threadIdx.x;
    bool m = (i < n) && tile_mask(g_s4[i], tile);

    __shared__ int wc[8];
    unsigned ball = __ballot_sync(0xffffffffu, m);
    if ((threadIdx.x & 31) == 0) wc[threadIdx.x >> 5] = __popc(ball);
    __syncthreads();
    if (threadIdx.x == 0) {
        int s = 0;
        #pragma unroll
        for (int w = 0; w < 8; ++w) s += wc[w];
        g_chunkCnt[tile][chunk] = s;
    }
}

// ---------------- kernel 6: per-tile scan of chunk counts ----------------
__global__ void tb_scan_kernel(int nchunk)
{
    __shared__ int s[NCHUNK_MAX];
    int tile = blockIdx.x;
    int t = threadIdx.x;
    int v = (t < nchunk) ? g_chunkCnt[tile][t] : 0;
    s[t] = v;
    __syncthreads();
    for (int d = 1; d < NCHUNK_MAX; d <<= 1) {
        int u = (t >= d) ? s[t - d] : 0;
        __syncthreads();
        s[t] += u;
        __syncthreads();
    }
    if (t < nchunk) g_chunkOff[tile][t] = s[t] - v;
    if (t == NCHUNK_MAX - 1) g_tileCount[tile] = s[t];
}

// ---------------- kernel 7: per-tile stable compaction (parallel) ----------------
__global__ void tb_scatter_kernel(int n)
{
    int chunk = blockIdx.x;
    int tile  = blockIdx.y;
    int tid   = threadIdx.x;
    int lane  = tid & 31;
    int warp  = tid >> 5;
    int i = chunk * 256 + tid;
    bool m = (i < n) && tile_mask(g_s4[i], tile);

    __shared__ int wc[8];
    unsigned ball = __ballot_sync(0xffffffffu, m);
    int pre = __popc(ball & ((1u << lane) - 1u));
    if (lane == 0) wc[warp] = __popc(ball);
    __syncthreads();
    int woff = 0;
    #pragma unroll
    for (int w = 0; w < 8; ++w)
        woff += (w < warp) ? wc[w] : 0;
    if (m) {
        int pos = g_chunkOff[tile][chunk] + woff + pre;
        g_q1[tile][pos] = g_s1[i];
        g_q2[tile][pos] = g_s2[i];
        g_q3[tile][pos] = g_s3[i];
    }
}

// ---------------- kernel 8: render ----------------
#define BATCH 128
__global__ void __launch_bounds__(128) render_kernel(float* __restrict__ out)
{
    int tilex = blockIdx.x;
    int tiley = blockIdx.y;
    int tile  = tiley * 4 + tilex;
    int px = tilex * TILE + threadIdx.x;
    int py = tiley * TILE + blockIdx.z * 4 + threadIdx.y;
    float fx = (float)px;
    float fy = (float)py;

    int cnt = g_tileCount[tile];

    __shared__ float4 sb1[BATCH];
    __shared__ float4 sb2[BATCH];
    __shared__ float2 sb3[BATCH];

    float T = 1.0f;
    float cr = 0.0f, cg = 0.0f, cbl = 0.0f, cd = 0.0f;
    int tid = threadIdx.y * 32 + threadIdx.x;

    for (int base = 0; base < cnt; base += BATCH) {
        int m = min(BATCH, cnt - base);
        if (tid < m) {
            sb1[tid] = g_q1[tile][base + tid];
            sb2[tid] = g_q2[tile][base + tid];
            sb3[tid] = g_q3[tile][base + tid];
        }
        __syncthreads();

        if (T >= TERM_T) {
            for (int k = 0; k < m; ++k) {
                float4 p1 = sb1[k];                 // mx, my, A', B'
                float4 p2 = sb2[k];                 // C', log2(op), depth, colR
                float dx = fx - p1.x;
                float dy = fy - p1.y;
                float t  = fmaf(dy, p1.w, dx * p1.z);
                float v  = dy * p2.x;
                float w  = fmaf(dy, v, p2.y);       // dy^2*C' + log2(op)
                float pw = fmaf(dx, t, w);          // log2(gw*op), <= log2(op)
                if (pw > SKIP_L2) {
                    float alpha = fminf(ex2f(pw), 0.99f);
                    float wgt = T * alpha;
                    float2 p3 = sb3[k];
                    cr  = fmaf(wgt, p2.w, cr);
                    cg  = fmaf(wgt, p3.x, cg);
                    cbl = fmaf(wgt, p3.y, cbl);
                    cd  = fmaf(wgt, p2.z, cd);
                    T  -= wgt;                      // T *= (1-alpha)
                    if (T < TERM_T) break;
                }
            }
        }
        __syncthreads();
        if (__syncthreads_and(T < TERM_T)) break;
    }

    int pix = py * W + px;
    out[pix * 3 + 0]     = cr  + T;   // sum(wgt*col) + (1 - acc), acc = 1 - T
    out[pix * 3 + 1]     = cg  + T;
    out[pix * 3 + 2]     = cbl + T;
    out[H * W * 3 + pix] = cd;
    out[H * W * 4 + pix] = 1.0f - T;
}

// ---------------- launch ----------------
extern "C" void kernel_launch(void* const* d_in, const int* in_sizes, int n_in,
                              void* d_out, int out_size)
{
    const float* means   = (const float*)d_in[0];
    const float* cov     = (const float*)d_in[1];
    const float* color   = (const float*)d_in[2];
    const float* opacity = (const float*)d_in[3];
    const float* depths  = (const float*)d_in[4];
    int n = in_sizes[4];
    if (n > MAXN) n = MAXN;

    int blocks = (n + 255) / 256;   // == NCHUNK

    zero_kernel<<<4, 1024>>>();
    prep_kernel<<<blocks, 256>>>(means, cov, color, opacity, depths, n);
    bucket_scan_kernel<<<1, 1024>>>();
    place_kernel<<<blocks, 256>>>(n);
    rank_scatter_kernel<<<blocks, 256>>>(n);
    tb_count_kernel<<<dim3(blocks, NTILES), 256>>>(n);
    tb_scan_kernel<<<NTILES, NCHUNK_MAX>>>(blocks);
    tb_scatter_kernel<<<dim3(blocks, NTILES), 256>>>(n);
    render_kernel<<<dim3(4, 4, 8), dim3(32, 4)>>>((float*)d_out);
}